// round 8
// baseline (speedup 1.0000x reference)
#include <cuda_runtime.h>
#include <cuda_bf16.h>
#include <cstdint>

#define B_    16
#define T_    1024
#define V_    8192
#define H_    1024
#define NBLK  128
#define BTV   134217728   // B_*T_*V_

// ---------------------------------------------------------------------------
// Device-global scratch (allocation is forbidden) + grid-barrier state.
//   g_A_hi/lo : bf16 split of hs, [m][k] with m = t*16 + b  (GEMM A)
//   g_W_hi/lo : bf16 split of Wy, [n][k]                    (GEMM B)
//   g_hT      : fp32 ping-pong h exchange in [j][b] layout
// ---------------------------------------------------------------------------
__device__ __nv_bfloat16 g_A_hi[(size_t)T_ * B_ * H_];
__device__ __nv_bfloat16 g_A_lo[(size_t)T_ * B_ * H_];
__device__ __nv_bfloat16 g_W_hi[(size_t)V_ * H_];
__device__ __nv_bfloat16 g_W_lo[(size_t)V_ * H_];
__device__ float         g_hT[2][B_ * H_];
__device__ unsigned      g_bar_count = 0;
__device__ unsigned      g_bar_sense = 0;

extern __shared__ char smem_raw[];

// ---------------------------------------------------------------------------
// PTX helpers (baseline sm_80 ISA only — tcgen05 is rejected by this
// toolchain's ptxas target)
// ---------------------------------------------------------------------------
__device__ __forceinline__ uint32_t smem_u32(const void* p) {
    uint32_t a;
    asm("{ .reg .u64 t; cvta.to.shared.u64 t, %1; cvt.u32.u64 %0, t; }"
        : "=r"(a) : "l"(p));
    return a;
}
__device__ __forceinline__ void cp16(uint32_t dst, const void* src) {
    asm volatile("cp.async.cg.shared.global [%0], [%1], 16;"
                 :: "r"(dst), "l"(src) : "memory");
}
__device__ __forceinline__ void ldsm_x4(uint32_t& r0, uint32_t& r1,
                                        uint32_t& r2, uint32_t& r3,
                                        uint32_t addr) {
    asm volatile("ldmatrix.sync.aligned.m8n8.x4.shared.b16 {%0,%1,%2,%3}, [%4];"
                 : "=r"(r0), "=r"(r1), "=r"(r2), "=r"(r3) : "r"(addr));
}
__device__ __forceinline__ void mma_bf16(float* d, const uint32_t* a,
                                         const uint32_t* b) {
    asm volatile(
        "mma.sync.aligned.m16n8k16.row.col.f32.bf16.bf16.f32 "
        "{%0,%1,%2,%3},{%4,%5,%6,%7},{%8,%9},{%0,%1,%2,%3};"
        : "+f"(d[0]), "+f"(d[1]), "+f"(d[2]), "+f"(d[3])
        : "r"(a[0]), "r"(a[1]), "r"(a[2]), "r"(a[3]), "r"(b[0]), "r"(b[1]));
}
__device__ __forceinline__ void bf16_split(float x, __nv_bfloat16& h,
                                           __nv_bfloat16& l) {
    h = __float2bfloat16(x);
    l = __float2bfloat16(x - __bfloat162float(h));
}

// ---------------------------------------------------------------------------
// Kernel 0: split Wy (fp32 [V,H]) into bf16 hi/lo.  2,097,152 float4 threads.
// ---------------------------------------------------------------------------
__global__ void __launch_bounds__(256)
prep_wy_kernel(const float* __restrict__ Wy)
{
    size_t i = (size_t)blockIdx.x * 256 + threadIdx.x;   // < V_*H_/4
    float4 v = __ldg((const float4*)Wy + i);
    __nv_bfloat16 h0, l0, h1, l1, h2, l2, h3, l3;
    bf16_split(v.x, h0, l0);  bf16_split(v.y, h1, l1);
    bf16_split(v.z, h2, l2);  bf16_split(v.w, h3, l3);
    ushort4 hv, lv;
    hv.x = reinterpret_cast<unsigned short&>(h0);
    hv.y = reinterpret_cast<unsigned short&>(h1);
    hv.z = reinterpret_cast<unsigned short&>(h2);
    hv.w = reinterpret_cast<unsigned short&>(h3);
    lv.x = reinterpret_cast<unsigned short&>(l0);
    lv.y = reinterpret_cast<unsigned short&>(l1);
    lv.z = reinterpret_cast<unsigned short&>(l2);
    lv.w = reinterpret_cast<unsigned short&>(l3);
    ((ushort4*)g_W_hi)[i] = hv;
    ((ushort4*)g_W_lo)[i] = lv;
}

// ---------------------------------------------------------------------------
// Kernel 1: persistent RNN recurrence (verified round-6 structure; only the
// h_t store targets changed to bf16 hi/lo).
//   h_t[b][j] = tanh( Wx_w[j, x[b,t]] + Wx_b[j] + sum_k h_{t-1}[b][k]*Wh[j][k] )
// 128 blocks x 128 threads; block owns 8 j, all 16 b. One grid barrier/step.
// ---------------------------------------------------------------------------
__global__ void __launch_bounds__(128, 1)
rnn_recurrence_kernel(const int*   __restrict__ x,
                      const float* __restrict__ h0,
                      const float* __restrict__ Wx,
                      const float* __restrict__ Wxb,
                      const float* __restrict__ Wh,
                      float*       __restrict__ out,
                      int out_size)
{
    float* h_s  = (float*)smem_raw;          // 16384 floats: h_{t-1} as [k][b]
    float* wh_s = (float*)smem_raw + 16384;  //  8192 floats: Wh rows [jl][k]

    const int tid = threadIdx.x;
    const int j0  = (int)blockIdx.x * 8;
    const int jl  = tid >> 4;                // 0..7
    const int j   = j0 + jl;
    const int b   = tid & 15;

    {   // one-time: stage this block's 8 Wh rows (32 KB)
        const float4* src = (const float4*)(Wh + (size_t)j0 * H_);
        float4*       dst = (float4*)wh_s;
        #pragma unroll
        for (int s = 0; s < 16; s++)
            dst[tid + s * 128] = src[tid + s * 128];
    }

    const float  wxb   = Wxb[j];
    const float* wxrow = Wx + (size_t)j * V_;
    const int*   xrow  = x + b * T_;
    const float* whs   = wh_s + jl * H_;
    const int    exch  = jl * 16 + b;        // [j][b] offset within g_hT slot

    for (int t = 0; t < T_; t++) {
        // ---- stage h_{t-1} into shared as [k][b] ----
        if (t == 0) {
            for (int i = tid; i < B_ * H_; i += 128)
                h_s[i] = h0[(i & 15) * H_ + (i >> 4)];   // transpose h0
        } else {
            const float4* src = (const float4*)(g_hT[(t - 1) & 1]);
            float4*       dst = (float4*)h_s;
            #pragma unroll
            for (int s = 0; s < 32; s++)
                dst[tid + s * 128] = __ldcg(src + tid + s * 128);
        }
        __syncthreads();

        // ---- embedding gather (L2-resident Wx) ----
        int   xi = __ldg(xrow + t);
        float e  = __ldg(wxrow + xi) + wxb;

        // ---- dot(h_{t-1}[b][:], Wh[j][:]) ----
        float a0 = 0.f, a1 = 0.f, a2 = 0.f, a3 = 0.f;
        float a4 = 0.f, a5 = 0.f, a6 = 0.f, a7 = 0.f;
        #pragma unroll 4
        for (int k = 0; k < H_; k += 8) {
            float4 w0 = *(const float4*)(whs + k);
            float4 w1 = *(const float4*)(whs + k + 4);
            a0 += w0.x * h_s[(k + 0) * 16 + b];
            a1 += w0.y * h_s[(k + 1) * 16 + b];
            a2 += w0.z * h_s[(k + 2) * 16 + b];
            a3 += w0.w * h_s[(k + 3) * 16 + b];
            a4 += w1.x * h_s[(k + 4) * 16 + b];
            a5 += w1.y * h_s[(k + 5) * 16 + b];
            a6 += w1.z * h_s[(k + 6) * 16 + b];
            a7 += w1.w * h_s[(k + 7) * 16 + b];
        }
        float dot = ((a0 + a1) + (a2 + a3)) + ((a4 + a5) + (a6 + a7));
        float hv  = tanhf(e + dot);

        // exchange buffer (coalesced, [j][b]) + GEMM A as bf16 hi/lo [m][j]
        __stcg(&g_hT[t & 1][(size_t)j0 * 16 + exch], hv);
        {
            __nv_bfloat16 hb, lb;
            bf16_split(hv, hb, lb);
            size_t mi = ((size_t)t * 16 + b) * H_ + j;
            g_A_hi[mi] = hb;
            g_A_lo[mi] = lb;
        }

        if (t == T_ - 1 && out_size >= BTV + B_ * H_)
            out[(size_t)BTV + b * H_ + j] = hv;          // h_final [B][H]

        // ---- grid barrier (sense-reversing, replay-safe) ----
        __threadfence();
        __syncthreads();
        if (tid == 0) {
            unsigned gen = *((volatile unsigned*)&g_bar_sense);
            unsigned arr = atomicAdd(&g_bar_count, 1u);
            if (arr == NBLK - 1) {
                atomicExch(&g_bar_count, 0u);
                __threadfence();
                atomicAdd(&g_bar_sense, 1u);
            } else {
                while (*((volatile unsigned*)&g_bar_sense) == gen) { }
            }
        }
        __syncthreads();
        __threadfence();
    }
}

// ---------------------------------------------------------------------------
// Kernel 2: output GEMM via mma.sync bf16, 3-term split (hh + hl + lh).
//   logits[b][t][v] = sum_k A[m][k]*W[v][k] + Wyb[v],  m = t*16+b
// 128x128 tile, BK=32, 2-stage cp.async pipeline, 8 warps as 2(m) x 4(n),
// warp tile 64x32: 4 m-frags x 4 n-frags, 48 HMMA per k16.
// ---------------------------------------------------------------------------
#define GBK        32
#define LDSS       40                      // smem row stride in bf16 (80 B)
#define ARR_BYTES  (128 * LDSS * 2)        // 10240 per matrix array
#define STG_BYTES  (4 * ARR_BYTES)         // 40960 per stage

__device__ __forceinline__ void load_stage(uint32_t st_base, int kc, int tid,
                                           const __nv_bfloat16* Ah,
                                           const __nv_bfloat16* Al,
                                           const __nv_bfloat16* Bh,
                                           const __nv_bfloat16* Bl)
{
    #pragma unroll
    for (int q = 0; q < 2; q++) {
        int idx = tid + q * 256;
        int row = idx >> 2;
        int c   = idx & 3;
        uint32_t doff = (uint32_t)row * (LDSS * 2) + c * 16;
        size_t   goff = (size_t)row * H_ + (size_t)kc * GBK + c * 8;
        cp16(st_base + 0 * ARR_BYTES + doff, Ah + goff);
        cp16(st_base + 1 * ARR_BYTES + doff, Al + goff);
        cp16(st_base + 2 * ARR_BYTES + doff, Bh + goff);
        cp16(st_base + 3 * ARR_BYTES + doff, Bl + goff);
    }
}

__global__ void __launch_bounds__(256, 1)
gemm_bf16_kernel(const float* __restrict__ Wyb,
                 float*       __restrict__ out)
{
    const int tid  = threadIdx.x;
    const int lane = tid & 31;
    const int wid  = tid >> 5;
    const int n0   = (int)blockIdx.x * 128;
    const int m0   = (int)blockIdx.y * 128;
    const int wm   = wid >> 2;             // 0..1  -> m offset 64*wm
    const int wn   = wid & 3;              // 0..3  -> n offset 32*wn

    const uint32_t smb = smem_u32(smem_raw);

    const __nv_bfloat16* Ah = g_A_hi + (size_t)m0 * H_;
    const __nv_bfloat16* Al = g_A_lo + (size_t)m0 * H_;
    const __nv_bfloat16* Bh = g_W_hi + (size_t)n0 * H_;
    const __nv_bfloat16* Bl = g_W_lo + (size_t)n0 * H_;

    float acc[4][4][4];
    #pragma unroll
    for (int mf = 0; mf < 4; mf++)
        #pragma unroll
        for (int nf = 0; nf < 4; nf++)
            #pragma unroll
            for (int r = 0; r < 4; r++) acc[mf][nf][r] = 0.0f;

    load_stage(smb, 0, tid, Ah, Al, Bh, Bl);
    asm volatile("cp.async.commit_group;" ::: "memory");

    // fragment address components
    const int ar = lane & 15;              // A: row within 16
    const int ak = (lane >> 4) * 8;        // A: k-half select
    const int br = (lane & 7) + ((lane >> 4) & 1) * 8;  // B: n row (2 frags)
    const int bk = ((lane >> 3) & 1) * 8;               // B: k-half select

    #pragma unroll 1
    for (int kc = 0; kc < H_ / GBK; kc++) {
        const int st = kc & 1;
        if (kc < H_ / GBK - 1) {
            load_stage(smb + (uint32_t)(st ^ 1) * STG_BYTES, kc + 1, tid,
                       Ah, Al, Bh, Bl);
            asm volatile("cp.async.commit_group;" ::: "memory");
            asm volatile("cp.async.wait_group 1;" ::: "memory");
        } else {
            asm volatile("cp.async.wait_group 0;" ::: "memory");
        }
        __syncthreads();

        const uint32_t sA_hi = smb + (uint32_t)st * STG_BYTES;
        const uint32_t sA_lo = sA_hi + ARR_BYTES;
        const uint32_t sB_hi = sA_hi + 2 * ARR_BYTES;
        const uint32_t sB_lo = sA_hi + 3 * ARR_BYTES;

        #pragma unroll
        for (int ks = 0; ks < 2; ks++) {
            const int kb = ks * 16;
            uint32_t ahi[4][4], alo[4][4];
            #pragma unroll
            for (int mf = 0; mf < 4; mf++) {
                uint32_t off =
                    ((uint32_t)(wm * 64 + mf * 16 + ar) * LDSS + kb + ak) * 2;
                ldsm_x4(ahi[mf][0], ahi[mf][1], ahi[mf][2], ahi[mf][3],
                        sA_hi + off);
                ldsm_x4(alo[mf][0], alo[mf][1], alo[mf][2], alo[mf][3],
                        sA_lo + off);
            }
            uint32_t bhi[4][2], blo[4][2];
            #pragma unroll
            for (int g = 0; g < 2; g++) {
                uint32_t off =
                    ((uint32_t)(wn * 32 + g * 16 + br) * LDSS + kb + bk) * 2;
                uint32_t r0, r1, r2, r3;
                ldsm_x4(r0, r1, r2, r3, sB_hi + off);
                bhi[2 * g][0] = r0;  bhi[2 * g][1] = r1;
                bhi[2 * g + 1][0] = r2;  bhi[2 * g + 1][1] = r3;
                ldsm_x4(r0, r1, r2, r3, sB_lo + off);
                blo[2 * g][0] = r0;  blo[2 * g][1] = r1;
                blo[2 * g + 1][0] = r2;  blo[2 * g + 1][1] = r3;
            }
            #pragma unroll
            for (int mf = 0; mf < 4; mf++)
                #pragma unroll
                for (int nf = 0; nf < 4; nf++) {
                    mma_bf16(acc[mf][nf], ahi[mf], bhi[nf]);
                    mma_bf16(acc[mf][nf], ahi[mf], blo[nf]);
                    mma_bf16(acc[mf][nf], alo[mf], bhi[nf]);
                }
        }
        __syncthreads();
    }

    // ---- epilogue: bias + scatter to logits [b][t][v] ----
    float2 bias[4];
    #pragma unroll
    for (int nf = 0; nf < 4; nf++)
        bias[nf] = __ldg((const float2*)
                         (Wyb + n0 + wn * 32 + nf * 8 + 2 * (lane & 3)));
    #pragma unroll
    for (int mf = 0; mf < 4; mf++) {
        int m1 = m0 + wm * 64 + mf * 16 + (lane >> 2);
        int m2 = m1 + 8;
        float* p1 = out + ((size_t)(m1 & 15) * T_ + (m1 >> 4)) * V_;
        float* p2 = out + ((size_t)(m2 & 15) * T_ + (m2 >> 4)) * V_;
        #pragma unroll
        for (int nf = 0; nf < 4; nf++) {
            int n = n0 + wn * 32 + nf * 8 + 2 * (lane & 3);
            float2 v1 = make_float2(acc[mf][nf][0] + bias[nf].x,
                                    acc[mf][nf][1] + bias[nf].y);
            float2 v2 = make_float2(acc[mf][nf][2] + bias[nf].x,
                                    acc[mf][nf][3] + bias[nf].y);
            *(float2*)(p1 + n) = v1;
            *(float2*)(p2 + n) = v2;
        }
    }
}

// ---------------------------------------------------------------------------
// Launch
// ---------------------------------------------------------------------------
extern "C" void kernel_launch(void* const* d_in, const int* in_sizes, int n_in,
                              void* d_out, int out_size) {
    const int*   x   = (const int*)  d_in[0];   // [B,T] int32
    const float* h0  = (const float*)d_in[1];   // [B,H]
    const float* Wx  = (const float*)d_in[2];   // [H,V]
    const float* Wxb = (const float*)d_in[3];   // [H]
    const float* Wh  = (const float*)d_in[4];   // [H,H]
    const float* Wy  = (const float*)d_in[5];   // [V,H]
    const float* Wyb = (const float*)d_in[6];   // [V]
    float* out = (float*)d_out;

    // Wy bf16 split (independent of the recurrence; ~20 us)
    prep_wy_kernel<<<(V_ * H_ / 4) / 256, 256>>>(Wy);

    const int smem_rnn = (B_ * H_ + 8 * H_) * (int)sizeof(float);   // 96 KB
    cudaFuncSetAttribute(rnn_recurrence_kernel,
                         cudaFuncAttributeMaxDynamicSharedMemorySize, smem_rnn);
    rnn_recurrence_kernel<<<NBLK, 128, smem_rnn>>>(x, h0, Wx, Wxb, Wh,
                                                   out, out_size);

    const int smem_g = 2 * STG_BYTES;                               // 80 KB
    cudaFuncSetAttribute(gemm_bf16_kernel,
                         cudaFuncAttributeMaxDynamicSharedMemorySize, smem_g);
    dim3 grid(V_ / 128, (T_ * B_) / 128);                           // (64, 128)
    gemm_bf16_kernel<<<grid, 256, smem_g>>>(Wyb, out);
}

// round 9
// speedup vs baseline: 1.3047x; 1.3047x over previous
#include <cuda_runtime.h>
#include <cstdint>

#define B_    16
#define T_    1024
#define V_    8192
#define H_    1024
#define NBLK  128
#define BTV   134217728   // B_*T_*V_

// ---------------------------------------------------------------------------
// Device-global scratch (allocation is forbidden) + grid-barrier state.
//   g_hs : [t][k][b] fp32 (GEMM A tiles; tile rows m = t*16+b)
//   g_hT : ping-pong h exchange in PAIR layout: idx = (j>>1)*32 + b*2 + (j&1)
// ---------------------------------------------------------------------------
__device__ float    g_hs[(size_t)T_ * B_ * H_];   // 64 MB
__device__ float    g_hT[2][B_ * H_];
__device__ unsigned g_bar_count = 0;
__device__ unsigned g_bar_sense = 0;

extern __shared__ float smem_dyn[];

// ---------------------------------------------------------------------------
// Packed f32x2 helpers (FFMA2 path: only reachable via PTX fma.rn.f32x2)
// ---------------------------------------------------------------------------
__device__ __forceinline__ unsigned long long pack2(float x, float y) {
    unsigned long long r;
    asm("mov.b64 %0, {%1, %2};" : "=l"(r) : "f"(x), "f"(y));
    return r;
}
__device__ __forceinline__ void fma2(unsigned long long &d,
                                     unsigned long long a,
                                     unsigned long long b) {
    asm("fma.rn.f32x2 %0, %1, %2, %0;" : "+l"(d) : "l"(a), "l"(b));
}
__device__ __forceinline__ void unpack2(unsigned long long v, float &lo, float &hi) {
    asm("mov.b64 {%0, %1}, %2;" : "=f"(lo), "=f"(hi) : "l"(v));
}

// ---------------------------------------------------------------------------
// Kernel 1: persistent RNN recurrence.
//   h_t[b][j] = tanh( Wx_w[j, x[b,t]] + Wx_b[j] + sum_k h_{t-1}[b][k]*Wh[j][k] )
// 128 blocks x 128 threads; block owns 8 j, all 16 b. Thread (jl=tid>>4, b=tid&15).
// h held in PAIR layout [k/2][b][2] -> conflict-free LDS.64 + fma.f32x2.
// One grid barrier per step (sense-reversing; safe across graph replays).
// ---------------------------------------------------------------------------
__global__ void __launch_bounds__(128, 1)
rnn_recurrence_kernel(const int*   __restrict__ x,
                      const float* __restrict__ h0,
                      const float* __restrict__ Wx,
                      const float* __restrict__ Wxb,
                      const float* __restrict__ Wh,
                      float*       __restrict__ out,
                      int out_size)
{
    float* h_s  = smem_dyn;            // 16384 floats: h_{t-1} pair layout
    float* wh_s = smem_dyn + 16384;    //  8192 floats: Wh rows [jl][k]

    const int tid = threadIdx.x;
    const int j0  = (int)blockIdx.x * 8;
    const int jl  = tid >> 4;          // 0..7
    const int j   = j0 + jl;
    const int b   = tid & 15;

    {   // one-time: stage this block's 8 Wh rows (32 KB)
        const float4* src = (const float4*)(Wh + (size_t)j0 * H_);
        float4*       dst = (float4*)wh_s;
        #pragma unroll
        for (int s = 0; s < 16; s++)
            dst[tid + s * 128] = src[tid + s * 128];
    }

    const float  wxb   = Wxb[j];
    const float* wxrow = Wx + (size_t)j * V_;
    const int*   xrow  = x + b * T_;
    const float* whs   = wh_s + jl * H_;
    // pair-layout index for this thread's h value: ((j>>1)*32 + b*2 + (j&1))
    const int    pidx  = ((j >> 1) << 5) + (b << 1) + (j & 1);
    float*       hout  = g_hs + (size_t)j * 16 + b;    // [t][k][b], k = j

    for (int t = 0; t < T_; t++) {
        // ---- stage h_{t-1} into shared (pair layout) ----
        if (t == 0) {
            for (int i = tid; i < B_ * H_; i += 128) {
                int bb = (i >> 1) & 15;
                int kk = ((i >> 5) << 1) | (i & 1);
                h_s[i] = h0[bb * H_ + kk];
            }
        } else {
            const float4* src = (const float4*)(g_hT[(t - 1) & 1]);
            float4*       dst = (float4*)h_s;
            #pragma unroll
            for (int s = 0; s < 32; s++)
                dst[tid + s * 128] = __ldcg(src + tid + s * 128);
        }
        __syncthreads();

        // ---- embedding gather (L2-resident Wx) ----
        int   xi = __ldg(xrow + t);
        float e  = __ldg(wxrow + xi) + wxb;

        // ---- dot(h_{t-1}[b][:], Wh[j][:]) via f32x2, 8 chains ----
        unsigned long long acc2[8];
        #pragma unroll
        for (int i = 0; i < 8; i++) acc2[i] = 0ull;

        const char* hbase = (const char*)h_s + b * 8;   // + kp*128 per pair
        #pragma unroll 2
        for (int kp = 0; kp < 512; kp += 8) {           // 16 k per iter
            ulonglong2 w01 = *(const ulonglong2*)(whs + 2 * kp);
            ulonglong2 w23 = *(const ulonglong2*)(whs + 2 * kp + 4);
            ulonglong2 w45 = *(const ulonglong2*)(whs + 2 * kp + 8);
            ulonglong2 w67 = *(const ulonglong2*)(whs + 2 * kp + 12);
            const char* hp = hbase + (size_t)kp * 128;
            fma2(acc2[0], *(const unsigned long long*)(hp + 0 * 128), w01.x);
            fma2(acc2[1], *(const unsigned long long*)(hp + 1 * 128), w01.y);
            fma2(acc2[2], *(const unsigned long long*)(hp + 2 * 128), w23.x);
            fma2(acc2[3], *(const unsigned long long*)(hp + 3 * 128), w23.y);
            fma2(acc2[4], *(const unsigned long long*)(hp + 4 * 128), w45.x);
            fma2(acc2[5], *(const unsigned long long*)(hp + 5 * 128), w45.y);
            fma2(acc2[6], *(const unsigned long long*)(hp + 6 * 128), w67.x);
            fma2(acc2[7], *(const unsigned long long*)(hp + 7 * 128), w67.y);
        }
        float dot = 0.0f;
        {
            float s0 = 0.f, s1 = 0.f;
            #pragma unroll
            for (int i = 0; i < 8; i += 2) {
                float l, h;
                unpack2(acc2[i], l, h);     s0 += l + h;
                unpack2(acc2[i + 1], l, h); s1 += l + h;
            }
            dot = s0 + s1;
        }
        float hv = tanhf(e + dot);

        // exchange buffer (pair layout; fully coalesced) + GEMM A matrix
        __stcg(&g_hT[t & 1][pidx], hv);
        __stcg(hout + (size_t)t * (B_ * H_), hv);

        if (t == T_ - 1 && out_size >= BTV + B_ * H_)
            out[(size_t)BTV + b * H_ + j] = hv;          // h_final [B][H]

        // ---- grid barrier (sense-reversing, replay-safe) ----
        __threadfence();
        __syncthreads();
        if (tid == 0) {
            unsigned gen = *((volatile unsigned*)&g_bar_sense);
            unsigned arr = atomicAdd(&g_bar_count, 1u);
            if (arr == NBLK - 1) {
                atomicExch(&g_bar_count, 0u);
                __threadfence();
                atomicAdd(&g_bar_sense, 1u);
            } else {
                while (*((volatile unsigned*)&g_bar_sense) == gen) { }
            }
        }
        __syncthreads();
        __threadfence();
    }
}

// ---------------------------------------------------------------------------
// Kernel 2: output GEMM (FFMA2), conflict-free interleaved-quad micro-tiles.
//   logits[b][t][v] = sum_k hs[t][b][k] * Wy[v][k] + Wyb[v]
// A[m][k] = g_hs[t][k][b], m = t*16+b. 128x128x16 tiles, 256 threads.
// Thread (tm=tid>>4, tn=tid&15) owns m in {tm*4..+3, 64+tm*4..+3},
// n in {tn*4..+3, 64+tn*4..+3}: every LDS.128 spans a contiguous 256 B
// across the 16 lanes -> zero bank conflicts (R6's 32B-stride map had 2-way).
// ---------------------------------------------------------------------------
#define BK   16
#define LDAS 132   // 128 + pad 4

__global__ void __launch_bounds__(256)
gemm_logits_kernel(const float* __restrict__ Wy,
                   const float* __restrict__ Wyb,
                   float*       __restrict__ out)
{
    __shared__ float As[BK][LDAS];
    __shared__ float Bs[BK][LDAS];

    const int tid = threadIdx.x;
    const int tn  = tid & 15;
    const int tm  = tid >> 4;
    const int n0  = (int)blockIdx.x * 128;
    const int t0  = (int)blockIdx.y * 8;     // m0 = t0*16

    // A loader: [t][k][b] -> As[k][t_local*16+b] (verified R6 loader)
    const int a_t = tid >> 5;                // 0..7
    const int a_k = (tid & 31) >> 1;         // 0..15
    const int a_b = (tid & 1) * 8;           // 0 or 8
    const float* Ag = g_hs + (size_t)(t0 + a_t) * (B_ * H_) + a_k * 16 + a_b;

    // B loader: row n = tid>>1, k-offset (tid&1)*8
    const int b_n = tid >> 1;
    const int b_k = (tid & 1) * 8;
    const float* Bg = Wy + (size_t)(n0 + b_n) * H_ + b_k;

    unsigned long long acc[8][4];
    #pragma unroll
    for (int i = 0; i < 8; i++)
        #pragma unroll
        for (int jj = 0; jj < 4; jj++) acc[i][jj] = 0ull;

    for (int k0 = 0; k0 < H_; k0 += BK) {
        float4 av0 = __ldg((const float4*)(Ag + (size_t)k0 * 16));
        float4 av1 = __ldg((const float4*)(Ag + (size_t)k0 * 16 + 4));
        float4 bv0 = __ldg((const float4*)(Bg + k0));
        float4 bv1 = __ldg((const float4*)(Bg + k0 + 4));
        __syncthreads();
        *(float4*)&As[a_k][a_t * 16 + a_b]     = av0;
        *(float4*)&As[a_k][a_t * 16 + a_b + 4] = av1;
        Bs[b_k + 0][b_n] = bv0.x;  Bs[b_k + 1][b_n] = bv0.y;
        Bs[b_k + 2][b_n] = bv0.z;  Bs[b_k + 3][b_n] = bv0.w;
        Bs[b_k + 4][b_n] = bv1.x;  Bs[b_k + 5][b_n] = bv1.y;
        Bs[b_k + 6][b_n] = bv1.z;  Bs[b_k + 7][b_n] = bv1.w;
        __syncthreads();

        #pragma unroll
        for (int k = 0; k < BK; k++) {
            float4 aq0 = *(const float4*)&As[k][tm * 4];
            float4 aq1 = *(const float4*)&As[k][64 + tm * 4];
            ulonglong2 b01 = *(const ulonglong2*)&Bs[k][tn * 4];
            ulonglong2 b23 = *(const ulonglong2*)&Bs[k][64 + tn * 4];
            unsigned long long b2[4] = { b01.x, b01.y, b23.x, b23.y };
            float am[8] = { aq0.x, aq0.y, aq0.z, aq0.w,
                            aq1.x, aq1.y, aq1.z, aq1.w };
            #pragma unroll
            for (int i = 0; i < 8; i++) {
                unsigned long long a2 = pack2(am[i], am[i]);
                #pragma unroll
                for (int jj = 0; jj < 4; jj++) fma2(acc[i][jj], a2, b2[jj]);
            }
        }
    }

    // ---- epilogue: bias + scatter to logits [b][t][v] ----
    float4 bias0 = __ldg((const float4*)(Wyb + n0 + tn * 4));
    float4 bias1 = __ldg((const float4*)(Wyb + n0 + 64 + tn * 4));
    #pragma unroll
    for (int i = 0; i < 8; i++) {
        int m_tile = (i < 4) ? (tm * 4 + i) : (64 + tm * 4 + (i - 4));
        int m  = t0 * 16 + m_tile;
        int tt = m >> 4;
        int bb = m & 15;
        float* orow = out + ((size_t)bb * T_ + tt) * V_ + n0;
        float l0, h0v, l1, h1v;
        unpack2(acc[i][0], l0, h0v);
        unpack2(acc[i][1], l1, h1v);
        float4 v0 = make_float4(l0 + bias0.x, h0v + bias0.y,
                                l1 + bias0.z, h1v + bias0.w);
        *(float4*)(orow + tn * 4) = v0;
        unpack2(acc[i][2], l0, h0v);
        unpack2(acc[i][3], l1, h1v);
        float4 v1 = make_float4(l0 + bias1.x, h0v + bias1.y,
                                l1 + bias1.z, h1v + bias1.w);
        *(float4*)(orow + 64 + tn * 4) = v1;
    }
}

// ---------------------------------------------------------------------------
// Launch
// ---------------------------------------------------------------------------
extern "C" void kernel_launch(void* const* d_in, const int* in_sizes, int n_in,
                              void* d_out, int out_size) {
    const int*   x   = (const int*)  d_in[0];   // [B,T] int32
    const float* h0  = (const float*)d_in[1];   // [B,H]
    const float* Wx  = (const float*)d_in[2];   // [H,V]
    const float* Wxb = (const float*)d_in[3];   // [H]
    const float* Wh  = (const float*)d_in[4];   // [H,H]
    const float* Wy  = (const float*)d_in[5];   // [V,H]
    const float* Wyb = (const float*)d_in[6];   // [V]
    float* out = (float*)d_out;

    const int smem_rnn = (B_ * H_ + 8 * H_) * (int)sizeof(float);   // 96 KB
    cudaFuncSetAttribute(rnn_recurrence_kernel,
                         cudaFuncAttributeMaxDynamicSharedMemorySize, smem_rnn);
    rnn_recurrence_kernel<<<NBLK, 128, smem_rnn>>>(x, h0, Wx, Wxb, Wh,
                                                   out, out_size);

    dim3 grid(V_ / 128, (T_ * B_) / 128);   // (64, 128)
    gemm_logits_kernel<<<grid, 256>>>(Wy, Wyb, out);
}